// round 2
// baseline (speedup 1.0000x reference)
#include <cuda_runtime.h>
#include <cfloat>

#define EPS_S   0.01f
#define INV_EPS 100.0f
#define LOG_MU  -6.93146200f   /* log(1/1024 + 1e-8) */
#define BN_EPS  1e-5f

/* ---------------- scratch (device globals: no allocs allowed) -------------- */
__device__ float g_C[4 * 1024 * 1024];      /* cost matrix (kept as cost; exp fused) */
__device__ float g_u[4096], g_v[4096];
__device__ float g_rnx[4096], g_rny[4096];
__device__ float g_t[4 * 512 * 1024];       /* transported features, later blended */
__device__ float g_a1[4 * 256 * 1024];
__device__ float g_a2[4 * 256 * 1024];
__device__ float g_alpha[4 * 512 * 1024];
__device__ float g_cm[2048], g_rs[2048];
__device__ float g_scale[512], g_shift[512];

/* ---------------- small helpers ---------------- */
__device__ __forceinline__ float warpMax(float v) {
    #pragma unroll
    for (int o = 16; o; o >>= 1) v = fmaxf(v, __shfl_xor_sync(0xffffffffu, v, o));
    return v;
}
__device__ __forceinline__ float warpSum(float v) {
    #pragma unroll
    for (int o = 16; o; o >>= 1) v += __shfl_xor_sync(0xffffffffu, v, o);
    return v;
}

/* ---------------- 1/||x|| per point ---------------- */
__global__ __launch_bounds__(256) void rownorm(const float* __restrict__ x,
                                               float* __restrict__ rn) {
    int b = blockIdx.y;
    int i = blockIdx.x * 256 + threadIdx.x;
    const float* p = x + ((size_t)b * 512 << 10) + i;
    float s = 0.f;
    #pragma unroll 8
    for (int d = 0; d < 512; d++) {
        float v = p[(size_t)d << 10];
        s = fmaf(v, v, s);
    }
    rn[(b << 10) + i] = rsqrtf(s);
}

/* ---------------- SGEMM TN: C[i,j] = 1 - rnx[i]rny[j] * sum_d A[d,i]B[d,j] -- */
#define BM 128
#define BN 128
#define BK 16
__global__ __launch_bounds__(256) void gemm_tn_cost(
    const float* __restrict__ A, const float* __restrict__ B,
    const float* __restrict__ rnx, const float* __restrict__ rny,
    float* __restrict__ Cout) {
    int b = blockIdx.z;
    const float* Ab = A + (size_t)b * 512 * 1024;   /* [K=512][M=1024] */
    const float* Bb = B + (size_t)b * 512 * 1024;   /* [K=512][N=1024] */
    float* Cb = Cout + (size_t)b * 1024 * 1024;
    __shared__ float As[BK][BM];
    __shared__ float Bs[BK][BN];
    int tid = threadIdx.x;
    int tx = tid & 15, ty = tid >> 4;
    int m0 = blockIdx.x * BM, n0 = blockIdx.y * BN;
    float acc[8][8];
    #pragma unroll
    for (int i = 0; i < 8; i++)
        #pragma unroll
        for (int j = 0; j < 8; j++) acc[i][j] = 0.f;

    for (int k0 = 0; k0 < 512; k0 += BK) {
        #pragma unroll
        for (int l = 0; l < 2; l++) {
            int idx = tid + l * 256;
            int k = idx >> 5, m4 = idx & 31;
            float4 va = *(const float4*)(Ab + (size_t)(k0 + k) * 1024 + m0 + m4 * 4);
            *(float4*)&As[k][m4 * 4] = va;
            float4 vb = *(const float4*)(Bb + (size_t)(k0 + k) * 1024 + n0 + m4 * 4);
            *(float4*)&Bs[k][m4 * 4] = vb;
        }
        __syncthreads();
        #pragma unroll
        for (int k = 0; k < BK; k++) {
            float a[8], bb[8];
            *(float4*)a       = *(float4*)&As[k][ty * 8];
            *(float4*)(a + 4) = *(float4*)&As[k][ty * 8 + 4];
            *(float4*)bb       = *(float4*)&Bs[k][tx * 8];
            *(float4*)(bb + 4) = *(float4*)&Bs[k][tx * 8 + 4];
            #pragma unroll
            for (int i = 0; i < 8; i++)
                #pragma unroll
                for (int j = 0; j < 8; j++) acc[i][j] = fmaf(a[i], bb[j], acc[i][j]);
        }
        __syncthreads();
    }
    #pragma unroll
    for (int i = 0; i < 8; i++) {
        int m = m0 + ty * 8 + i;
        float rx = rnx[(b << 10) + m];
        float4 o0, o1;
        #pragma unroll
        for (int j = 0; j < 8; j++) {
            int n = n0 + tx * 8 + j;
            float v = 1.f - rx * rny[(b << 10) + n] * acc[i][j];
            if (j < 4) ((float*)&o0)[j] = v; else ((float*)&o1)[j - 4] = v;
        }
        *(float4*)(Cb + (size_t)m * 1024 + n0 + tx * 8)     = o0;
        *(float4*)(Cb + (size_t)m * 1024 + n0 + tx * 8 + 4) = o1;
    }
}

/* ---- SGEMM NT with fused pi: T[d,i] = sum_j A[d,j] * exp((u_i+v_j-C_ij)/eps)*1024 */
__global__ __launch_bounds__(256) void gemm_nt_t(
    const float* __restrict__ A,  /* style [512][1024], k=j inner */
    const float* __restrict__ Cc, /* cost [1024(i)][1024(j)] */
    const float* __restrict__ u, const float* __restrict__ v,
    float* __restrict__ T) {
    int b = blockIdx.z;
    const float* Ab = A + (size_t)b * 512 * 1024;
    const float* Pb = Cc + (size_t)b * 1024 * 1024;
    const float* ub = u + (b << 10);
    const float* vb = v + (b << 10);
    float* Tb = T + (size_t)b * 512 * 1024;
    __shared__ float As[BK][BM];
    __shared__ float Bs[BK][BN];
    int tid = threadIdx.x;
    int tx = tid & 15, ty = tid >> 4;
    int m0 = blockIdx.x * BM, n0 = blockIdx.y * BN;
    float acc[8][8];
    #pragma unroll
    for (int i = 0; i < 8; i++)
        #pragma unroll
        for (int j = 0; j < 8; j++) acc[i][j] = 0.f;

    for (int k0 = 0; k0 < 1024; k0 += BK) {
        #pragma unroll
        for (int l = 0; l < 2; l++) {
            int idx = tid + l * 256;
            int m = idx >> 2, k4 = idx & 3;
            float4 va = *(const float4*)(Ab + (size_t)(m0 + m) * 1024 + k0 + k4 * 4);
            As[k4 * 4 + 0][m] = va.x; As[k4 * 4 + 1][m] = va.y;
            As[k4 * 4 + 2][m] = va.z; As[k4 * 4 + 3][m] = va.w;
            float4 vc = *(const float4*)(Pb + (size_t)(n0 + m) * 1024 + k0 + k4 * 4);
            float ui = ub[n0 + m];
            float4 vv = *(const float4*)(vb + k0 + k4 * 4);
            Bs[k4 * 4 + 0][m] = __expf((ui + vv.x - vc.x) * INV_EPS) * 1024.f;
            Bs[k4 * 4 + 1][m] = __expf((ui + vv.y - vc.y) * INV_EPS) * 1024.f;
            Bs[k4 * 4 + 2][m] = __expf((ui + vv.z - vc.z) * INV_EPS) * 1024.f;
            Bs[k4 * 4 + 3][m] = __expf((ui + vv.w - vc.w) * INV_EPS) * 1024.f;
        }
        __syncthreads();
        #pragma unroll
        for (int k = 0; k < BK; k++) {
            float a[8], bb[8];
            *(float4*)a       = *(float4*)&As[k][ty * 8];
            *(float4*)(a + 4) = *(float4*)&As[k][ty * 8 + 4];
            *(float4*)bb       = *(float4*)&Bs[k][tx * 8];
            *(float4*)(bb + 4) = *(float4*)&Bs[k][tx * 8 + 4];
            #pragma unroll
            for (int i = 0; i < 8; i++)
                #pragma unroll
                for (int j = 0; j < 8; j++) acc[i][j] = fmaf(a[i], bb[j], acc[i][j]);
        }
        __syncthreads();
    }
    #pragma unroll
    for (int i = 0; i < 8; i++) {
        int m = m0 + ty * 8 + i;
        float4 o0, o1;
        #pragma unroll
        for (int j = 0; j < 8; j++) {
            float vvv = acc[i][j];
            if (j < 4) ((float*)&o0)[j] = vvv; else ((float*)&o1)[j - 4] = vvv;
        }
        *(float4*)(Tb + (size_t)m * 1024 + n0 + tx * 8)     = o0;
        *(float4*)(Tb + (size_t)m * 1024 + n0 + tx * 8 + 4) = o1;
    }
}

/* ---------------- Sinkhorn ---------------- */
__global__ void zero_uv(float* u, float* v) {
    int i = blockIdx.x * blockDim.x + threadIdx.x;
    if (i < 4096) { u[i] = 0.f; v[i] = 0.f; }
}

__global__ __launch_bounds__(256) void u_update(const float* __restrict__ C,
                                                const float* __restrict__ v,
                                                float* __restrict__ u) {
    int b = blockIdx.y, i = blockIdx.x, t = threadIdx.x;
    const float4* C4 = (const float4*)(C + ((size_t)(b << 10) + i) * 1024);
    const float4* V4 = (const float4*)(v + (b << 10));
    float4 c = C4[t], vv = V4[t];
    float x0 = (vv.x - c.x) * INV_EPS;
    float x1 = (vv.y - c.y) * INV_EPS;
    float x2 = (vv.z - c.z) * INV_EPS;
    float x3 = (vv.w - c.w) * INV_EPS;
    float mx = fmaxf(fmaxf(x0, x1), fmaxf(x2, x3));
    __shared__ float redm[8], redq[8];
    mx = warpMax(mx);
    if ((t & 31) == 0) redm[t >> 5] = mx;
    __syncthreads();
    if (t < 32) {
        float z = (t < 8) ? redm[t] : -FLT_MAX;
        #pragma unroll
        for (int o = 4; o; o >>= 1) z = fmaxf(z, __shfl_xor_sync(0xffffffffu, z, o));
        if (t == 0) redm[0] = z;
    }
    __syncthreads();
    float bm = redm[0];
    float s = __expf(x0 - bm) + __expf(x1 - bm) + __expf(x2 - bm) + __expf(x3 - bm);
    s = warpSum(s);
    if ((t & 31) == 0) redq[t >> 5] = s;
    __syncthreads();
    if (t == 0) {
        float z = 0.f;
        #pragma unroll
        for (int q = 0; q < 8; q++) z += redq[q];
        u[(b << 10) + i] = EPS_S * (LOG_MU - (bm + __logf(z)));
    }
}

__global__ __launch_bounds__(256) void v_update(const float* __restrict__ C,
                                                const float* __restrict__ u,
                                                float* __restrict__ v) {
    int b = blockIdx.y;
    int tx = threadIdx.x, ty = threadIdx.y;
    int j = blockIdx.x * 32 + tx;
    const float* p = C + (size_t)b * 1048576 + j;
    const float* ub = u + (b << 10);
    float m0 = -FLT_MAX, s0 = 0.f, m1 = -FLT_MAX, s1 = 0.f;
    for (int i = ty; i < 1024; i += 16) {
        float xa = (ub[i] - p[(size_t)i << 10]) * INV_EPS;
        float xb = (ub[i + 8] - p[(size_t)(i + 8) << 10]) * INV_EPS;
        float n0 = fmaxf(m0, xa);
        s0 = s0 * __expf(m0 - n0) + __expf(xa - n0); m0 = n0;
        float n1 = fmaxf(m1, xb);
        s1 = s1 * __expf(m1 - n1) + __expf(xb - n1); m1 = n1;
    }
    float mm = fmaxf(m0, m1);
    float ss = s0 * __expf(m0 - mm) + s1 * __expf(m1 - mm);
    __shared__ float sm[8][32], sq[8][32];
    sm[ty][tx] = mm; sq[ty][tx] = ss;
    __syncthreads();
    if (ty == 0) {
        float M = mm, S = ss;
        #pragma unroll
        for (int q = 1; q < 8; q++) {
            float m2 = sm[q][tx], s2 = sq[q][tx];
            float nm = fmaxf(M, m2);
            S = S * __expf(M - nm) + s2 * __expf(m2 - nm);
            M = nm;
        }
        v[(b << 10) + j] = EPS_S * (LOG_MU - (M + __logf(S)));
    }
}

/* ---------------- per-(b,c) mean / 1/std of content ---------------- */
__global__ __launch_bounds__(128) void cmstd(const float* __restrict__ x,
                                             float* __restrict__ cm,
                                             float* __restrict__ rs) {
    int bc = blockIdx.x, t = threadIdx.x;
    const float* p = x + ((size_t)bc << 10);
    float s = 0.f, q = 0.f;
    #pragma unroll
    for (int l = 0; l < 8; l++) {
        float v = p[t + l * 128];
        s += v; q = fmaf(v, v, q);
    }
    s = warpSum(s); q = warpSum(q);
    __shared__ float rsm[4], rqm[4];
    if ((t & 31) == 0) { rsm[t >> 5] = s; rqm[t >> 5] = q; }
    __syncthreads();
    if (t == 0) {
        float S = rsm[0] + rsm[1] + rsm[2] + rsm[3];
        float Q = rqm[0] + rqm[1] + rqm[2] + rqm[3];
        float mean = S * (1.f / 1024.f);
        float var = Q * (1.f / 1024.f) - mean * mean;
        cm[bc] = mean;
        rs[bc] = rsqrtf(fmaxf(var, 0.f) + 1e-5f);
    }
}

/* ---------------- BatchNorm stats (train mode): scale/shift ---------------- */
__global__ __launch_bounds__(256) void bnstats(const float* __restrict__ x,
                                               const float* __restrict__ g,
                                               const float* __restrict__ be,
                                               int CO, float* __restrict__ scale,
                                               float* __restrict__ shift) {
    int c = blockIdx.x, t = threadIdx.x;
    float s = 0.f, q = 0.f;
    #pragma unroll
    for (int l = 0; l < 16; l++) {
        int idx = t + (l << 8);
        int bb = idx >> 10, p = idx & 1023;
        float v = x[((size_t)(bb * CO + c) << 10) + p];
        s += v; q = fmaf(v, v, q);
    }
    s = warpSum(s); q = warpSum(q);
    __shared__ float rsm[8], rqm[8];
    if ((t & 31) == 0) { rsm[t >> 5] = s; rqm[t >> 5] = q; }
    __syncthreads();
    if (t == 0) {
        float S = 0.f, Q = 0.f;
        #pragma unroll
        for (int w = 0; w < 8; w++) { S += rsm[w]; Q += rqm[w]; }
        float mean = S * (1.f / 4096.f);
        float var = Q * (1.f / 4096.f) - mean * mean;
        float sc = g[c] * rsqrtf(fmaxf(var, 0.f) + BN_EPS);
        scale[c] = sc;
        shift[c] = be[c] - mean * sc;
    }
}

/* ---------------- t = alpha * (content - cm) * rs + t ---------------- */
__global__ __launch_bounds__(256) void blend(float* __restrict__ t,
                                             const float* __restrict__ alpha,
                                             const float* __restrict__ content,
                                             const float* __restrict__ cm,
                                             const float* __restrict__ rs, int n4) {
    int i = blockIdx.x * 256 + threadIdx.x;
    if (i >= n4) return;
    int ch = i >> 8;
    float m = cm[ch], r = rs[ch];
    float4 a = ((const float4*)alpha)[i];
    float4 x = ((const float4*)content)[i];
    float4 tv = ((float4*)t)[i];
    tv.x = fmaf(a.x, (x.x - m) * r, tv.x);
    tv.y = fmaf(a.y, (x.y - m) * r, tv.y);
    tv.z = fmaf(a.z, (x.z - m) * r, tv.z);
    tv.w = fmaf(a.w, (x.w - m) * r, tv.w);
    ((float4*)t)[i] = tv;
}

/* ---------------- direct 3x3 conv, register-tiled, shuffle halos ----------- */
/* Thread owns PXT contiguous pixels in one row; weights broadcast via LDS.128.
   Optional per-input-channel affine (fused BatchNorm apply). */
template <int OCT, int SROWS, int CIT>
__global__ __launch_bounds__(128) void conv3x3f(
    const float* __restrict__ src0, const float* __restrict__ src1, int csplit,
    const float* __restrict__ sc, const float* __restrict__ sh,
    int CI, int CO, const float* __restrict__ W, const float* __restrict__ bias,
    float* __restrict__ out, int relu) {
    constexpr int NT = 128;
    constexpr int PXT = SROWS * 32 / NT;     /* 4 or 1 */
    constexpr int CPR = 32 / PXT;            /* col groups per row */
    __shared__ float s_in[CIT][SROWS + 2][40];
    __shared__ float s_w[CIT][9][OCT];
    int b = blockIdx.x, oc0 = blockIdx.y * OCT, r0 = blockIdx.z * SROWS;
    int t = threadIdx.x;
    int row = t / CPR, cg = t % CPR, col0 = cg * PXT;

    float acc[OCT][PXT];
    #pragma unroll
    for (int o = 0; o < OCT; o++)
        #pragma unroll
        for (int p = 0; p < PXT; p++) acc[o][p] = 0.f;

    constexpr int TOTIN = CIT * (SROWS + 2) * 40;
    constexpr int TW = CIT * 9 * OCT;
    int use_aff = (sc != nullptr);

    #pragma unroll 1
    for (int ci0 = 0; ci0 < CI; ci0 += CIT) {
        /* fill input tile (left pad 4, right pad 4, zero halo) */
        #pragma unroll 1
        for (int idx = t; idx < TOTIN; idx += NT) {
            int ci = idx / ((SROWS + 2) * 40);
            int rem = idx - ci * ((SROWS + 2) * 40);
            int r = rem / 40, c = rem - r * 40;
            int gy = r0 + r - 1, gx = c - 4;
            float v = 0.f;
            if ((unsigned)gy < 32u && (unsigned)gx < 32u) {
                int cig = ci0 + ci;
                const float* s = (cig < csplit)
                    ? (src0 + ((size_t)(b * csplit + cig) << 10))
                    : (src1 + ((size_t)(b * (CI - csplit) + (cig - csplit)) << 10));
                v = s[(gy << 5) + gx];
                if (use_aff) v = fmaf(v, sc[cig], sh[cig]);
            }
            (&s_in[0][0][0])[idx] = v;
        }
        /* fill weights: s_w[ci][k][oc] */
        #pragma unroll 1
        for (int idx = t; idx < TW; idx += NT) {
            int ci = idx / (9 * OCT);
            int rem = idx - ci * (9 * OCT);
            int k = rem / OCT, oc = rem - k * OCT;
            float wv = 0.f;
            if (oc0 + oc < CO)
                wv = W[((size_t)(oc0 + oc) * CI + ci0 + ci) * 9 + k];
            (&s_w[0][0][0])[idx] = wv;
        }
        __syncthreads();
        #pragma unroll 1
        for (int ci = 0; ci < CIT; ci++) {
            #pragma unroll
            for (int ky = 0; ky < 3; ky++) {
                const float* rp = &s_in[ci][row + ky][4 + col0];
                float px[PXT + 2];
                if constexpr (PXT == 4) {
                    float4 pm = *(const float4*)rp;
                    px[1] = pm.x; px[2] = pm.y; px[3] = pm.z; px[4] = pm.w;
                    float up = __shfl_up_sync(0xffffffffu, pm.w, 1);
                    float dn = __shfl_down_sync(0xffffffffu, pm.x, 1);
                    px[0] = (cg == 0) ? 0.f : up;
                    px[5] = (cg == CPR - 1) ? 0.f : dn;
                } else {
                    float pm = rp[0];
                    px[1] = pm;
                    float up = __shfl_up_sync(0xffffffffu, pm, 1);
                    float dn = __shfl_down_sync(0xffffffffu, pm, 1);
                    px[0] = (cg == 0) ? 0.f : up;
                    px[2] = (cg == CPR - 1) ? 0.f : dn;
                }
                #pragma unroll
                for (int kx = 0; kx < 3; kx++) {
                    #pragma unroll
                    for (int o4 = 0; o4 < OCT / 4; o4++) {
                        float4 w4 = *(const float4*)&s_w[ci][ky * 3 + kx][o4 * 4];
                        #pragma unroll
                        for (int p = 0; p < PXT; p++) {
                            float v = px[kx + p];
                            acc[o4 * 4 + 0][p] = fmaf(v, w4.x, acc[o4 * 4 + 0][p]);
                            acc[o4 * 4 + 1][p] = fmaf(v, w4.y, acc[o4 * 4 + 1][p]);
                            acc[o4 * 4 + 2][p] = fmaf(v, w4.z, acc[o4 * 4 + 2][p]);
                            acc[o4 * 4 + 3][p] = fmaf(v, w4.w, acc[o4 * 4 + 3][p]);
                        }
                    }
                }
            }
        }
        __syncthreads();
    }
    /* epilogue */
    #pragma unroll
    for (int o = 0; o < OCT; o++) {
        if (oc0 + o >= CO) break;
        float bi = bias[oc0 + o];
        float* op = out + ((size_t)(b * CO + oc0 + o) << 10) + (r0 + row) * 32 + col0;
        if constexpr (PXT == 4) {
            float4 v;
            v.x = acc[o][0] + bi; v.y = acc[o][1] + bi;
            v.z = acc[o][2] + bi; v.w = acc[o][3] + bi;
            if (relu) {
                v.x = fmaxf(v.x, 0.f); v.y = fmaxf(v.y, 0.f);
                v.z = fmaxf(v.z, 0.f); v.w = fmaxf(v.w, 0.f);
            }
            *(float4*)op = v;
        } else {
            float v = acc[o][0] + bi;
            if (relu) v = fmaxf(v, 0.f);
            *op = v;
        }
    }
}

/* ---------------- host orchestration ---------------- */
extern "C" void kernel_launch(void* const* d_in, const int* in_sizes, int n_in,
                              void* d_out, int out_size) {
    const float* content = (const float*)d_in[0];
    const float* style   = (const float*)d_in[1];
    const float* w1 = (const float*)d_in[2];  const float* b1 = (const float*)d_in[3];
    const float* g1 = (const float*)d_in[4];  const float* be1 = (const float*)d_in[5];
    const float* w2 = (const float*)d_in[6];  const float* b2 = (const float*)d_in[7];
    const float* g2 = (const float*)d_in[8];  const float* be2 = (const float*)d_in[9];
    const float* w3 = (const float*)d_in[10]; const float* b3 = (const float*)d_in[11];
    const float* dw = (const float*)d_in[12]; const float* db = (const float*)d_in[13];
    float* out = (float*)d_out;
    (void)in_sizes; (void)n_in; (void)out_size;

    float *pC, *pu, *pv, *prnx, *prny, *pt, *pa1, *pa2, *palpha, *pcm, *prs, *pscale, *pshift;
    cudaGetSymbolAddress((void**)&pC, g_C);
    cudaGetSymbolAddress((void**)&pu, g_u);
    cudaGetSymbolAddress((void**)&pv, g_v);
    cudaGetSymbolAddress((void**)&prnx, g_rnx);
    cudaGetSymbolAddress((void**)&prny, g_rny);
    cudaGetSymbolAddress((void**)&pt, g_t);
    cudaGetSymbolAddress((void**)&pa1, g_a1);
    cudaGetSymbolAddress((void**)&pa2, g_a2);
    cudaGetSymbolAddress((void**)&palpha, g_alpha);
    cudaGetSymbolAddress((void**)&pcm, g_cm);
    cudaGetSymbolAddress((void**)&prs, g_rs);
    cudaGetSymbolAddress((void**)&pscale, g_scale);
    cudaGetSymbolAddress((void**)&pshift, g_shift);

    /* cosine-cost matrix */
    rownorm<<<dim3(4, 4), 256>>>(content, prnx);
    rownorm<<<dim3(4, 4), 256>>>(style, prny);
    gemm_tn_cost<<<dim3(8, 8, 4), 256>>>(content, style, prnx, prny, pC);

    /* Sinkhorn, 20 iterations */
    zero_uv<<<16, 256>>>(pu, pv);
    for (int it = 0; it < 20; it++) {
        u_update<<<dim3(1024, 4), 256>>>(pC, pv, pu);
        v_update<<<dim3(32, 4), dim3(32, 8)>>>(pC, pu, pv);
    }

    /* t = pi @ style_points, exp fused into B-tile load */
    gemm_nt_t<<<dim3(4, 8, 4), 256>>>(style, pC, pu, pv, pt);

    /* content per-channel mean/std */
    cmstd<<<2048, 128>>>(content, pcm, prs);

    /* alpha predictor (BN-apply fused into next conv's input load) */
    conv3x3f<16, 16, 8><<<dim3(4, 16, 2), 128>>>(pt, content, 512, nullptr, nullptr,
                                                 1024, 256, w1, b1, pa1, 1);
    bnstats<<<256, 256>>>(pa1, g1, be1, 256, pscale, pshift);
    conv3x3f<16, 16, 8><<<dim3(4, 16, 2), 128>>>(pa1, pa1, 256, pscale, pshift,
                                                 256, 256, w2, b2, pa2, 1);
    bnstats<<<256, 256>>>(pa2, g2, be2, 256, pscale, pshift);
    conv3x3f<16, 16, 8><<<dim3(4, 32, 2), 128>>>(pa2, pa2, 256, pscale, pshift,
                                                 256, 512, w3, b3, palpha, 0);

    /* t = alpha * c_normed + t, then decoder conv -> out */
    blend<<<2048, 256>>>(pt, palpha, content, pcm, prs, 4 * 512 * 256);
    conv3x3f<4, 4, 8><<<dim3(4, 1, 8), 128>>>(pt, pt, 512, nullptr, nullptr,
                                              512, 3, dw, db, out, 0);
}

// round 3
// speedup vs baseline: 1.5341x; 1.5341x over previous
#include <cuda_runtime.h>
#include <cfloat>

#define EPS_S   0.01f
#define INV_EPS 100.0f
#define LOG_MU  -6.93146200f   /* log(1/1024 + 1e-8) */
#define BN_EPS  1e-5f

/* ---------------- scratch (device globals: no allocs allowed) -------------- */
__device__ float g_C[4 * 1024 * 1024];      /* cost matrix (exp fused into GEMM) */
__device__ float g_u[4096], g_v[4096];
__device__ float g_rnx[4096], g_rny[4096];
__device__ float g_t[4 * 512 * 1024];
__device__ float g_a1[4 * 256 * 1024];
__device__ float g_a2[4 * 256 * 1024];
__device__ float g_alpha[4 * 512 * 1024];
__device__ float g_cm[2048], g_rs[2048];
__device__ float g_scale[512], g_shift[512];

/* ---------------- small helpers ---------------- */
__device__ __forceinline__ float warpMax(float v) {
    #pragma unroll
    for (int o = 16; o; o >>= 1) v = fmaxf(v, __shfl_xor_sync(0xffffffffu, v, o));
    return v;
}
__device__ __forceinline__ float warpSum(float v) {
    #pragma unroll
    for (int o = 16; o; o >>= 1) v += __shfl_xor_sync(0xffffffffu, v, o);
    return v;
}

/* ---------------- 1/||x|| per point ---------------- */
__global__ __launch_bounds__(256) void rownorm(const float* __restrict__ x,
                                               float* __restrict__ rn) {
    int b = blockIdx.y;
    int i = blockIdx.x * 256 + threadIdx.x;
    const float* p = x + ((size_t)b * 512 << 10) + i;
    float s = 0.f;
    #pragma unroll 8
    for (int d = 0; d < 512; d++) {
        float v = p[(size_t)d << 10];
        s = fmaf(v, v, s);
    }
    rn[(b << 10) + i] = rsqrtf(s);
}

/* ---------------- SGEMM TN: C[i,j] = 1 - rnx[i]rny[j] * sum_d A[d,i]B[d,j] -- */
#define BM 128
#define BN 128
#define BK 16
__global__ __launch_bounds__(256) void gemm_tn_cost(
    const float* __restrict__ A, const float* __restrict__ B,
    const float* __restrict__ rnx, const float* __restrict__ rny,
    float* __restrict__ Cout) {
    int b = blockIdx.z;
    const float* Ab = A + (size_t)b * 512 * 1024;
    const float* Bb = B + (size_t)b * 512 * 1024;
    float* Cb = Cout + (size_t)b * 1024 * 1024;
    __shared__ float As[BK][BM];
    __shared__ float Bs[BK][BN];
    int tid = threadIdx.x;
    int tx = tid & 15, ty = tid >> 4;
    int m0 = blockIdx.x * BM, n0 = blockIdx.y * BN;
    float acc[8][8];
    #pragma unroll
    for (int i = 0; i < 8; i++)
        #pragma unroll
        for (int j = 0; j < 8; j++) acc[i][j] = 0.f;

    for (int k0 = 0; k0 < 512; k0 += BK) {
        #pragma unroll
        for (int l = 0; l < 2; l++) {
            int idx = tid + l * 256;
            int k = idx >> 5, m4 = idx & 31;
            float4 va = *(const float4*)(Ab + (size_t)(k0 + k) * 1024 + m0 + m4 * 4);
            *(float4*)&As[k][m4 * 4] = va;
            float4 vb = *(const float4*)(Bb + (size_t)(k0 + k) * 1024 + n0 + m4 * 4);
            *(float4*)&Bs[k][m4 * 4] = vb;
        }
        __syncthreads();
        #pragma unroll
        for (int k = 0; k < BK; k++) {
            float a[8], bb[8];
            *(float4*)a       = *(float4*)&As[k][ty * 8];
            *(float4*)(a + 4) = *(float4*)&As[k][ty * 8 + 4];
            *(float4*)bb       = *(float4*)&Bs[k][tx * 8];
            *(float4*)(bb + 4) = *(float4*)&Bs[k][tx * 8 + 4];
            #pragma unroll
            for (int i = 0; i < 8; i++)
                #pragma unroll
                for (int j = 0; j < 8; j++) acc[i][j] = fmaf(a[i], bb[j], acc[i][j]);
        }
        __syncthreads();
    }
    #pragma unroll
    for (int i = 0; i < 8; i++) {
        int m = m0 + ty * 8 + i;
        float rx = rnx[(b << 10) + m];
        float4 o0, o1;
        #pragma unroll
        for (int j = 0; j < 8; j++) {
            int n = n0 + tx * 8 + j;
            float v = 1.f - rx * rny[(b << 10) + n] * acc[i][j];
            if (j < 4) ((float*)&o0)[j] = v; else ((float*)&o1)[j - 4] = v;
        }
        *(float4*)(Cb + (size_t)m * 1024 + n0 + tx * 8)     = o0;
        *(float4*)(Cb + (size_t)m * 1024 + n0 + tx * 8 + 4) = o1;
    }
}

/* ---- SGEMM NT with fused pi: T[d,i] = sum_j A[d,j] * exp((u_i+v_j-C_ij)/eps)*1024 */
__global__ __launch_bounds__(256) void gemm_nt_t(
    const float* __restrict__ A,
    const float* __restrict__ Cc,
    const float* __restrict__ u, const float* __restrict__ v,
    float* __restrict__ T) {
    int b = blockIdx.z;
    const float* Ab = A + (size_t)b * 512 * 1024;
    const float* Pb = Cc + (size_t)b * 1024 * 1024;
    const float* ub = u + (b << 10);
    const float* vb = v + (b << 10);
    float* Tb = T + (size_t)b * 512 * 1024;
    __shared__ float As[BK][BM];
    __shared__ float Bs[BK][BN];
    int tid = threadIdx.x;
    int tx = tid & 15, ty = tid >> 4;
    int m0 = blockIdx.x * BM, n0 = blockIdx.y * BN;
    float acc[8][8];
    #pragma unroll
    for (int i = 0; i < 8; i++)
        #pragma unroll
        for (int j = 0; j < 8; j++) acc[i][j] = 0.f;

    for (int k0 = 0; k0 < 1024; k0 += BK) {
        #pragma unroll
        for (int l = 0; l < 2; l++) {
            int idx = tid + l * 256;
            int m = idx >> 2, k4 = idx & 3;
            float4 va = *(const float4*)(Ab + (size_t)(m0 + m) * 1024 + k0 + k4 * 4);
            As[k4 * 4 + 0][m] = va.x; As[k4 * 4 + 1][m] = va.y;
            As[k4 * 4 + 2][m] = va.z; As[k4 * 4 + 3][m] = va.w;
            float4 vc = *(const float4*)(Pb + (size_t)(n0 + m) * 1024 + k0 + k4 * 4);
            float ui = ub[n0 + m];
            float4 vv = *(const float4*)(vb + k0 + k4 * 4);
            Bs[k4 * 4 + 0][m] = __expf((ui + vv.x - vc.x) * INV_EPS) * 1024.f;
            Bs[k4 * 4 + 1][m] = __expf((ui + vv.y - vc.y) * INV_EPS) * 1024.f;
            Bs[k4 * 4 + 2][m] = __expf((ui + vv.z - vc.z) * INV_EPS) * 1024.f;
            Bs[k4 * 4 + 3][m] = __expf((ui + vv.w - vc.w) * INV_EPS) * 1024.f;
        }
        __syncthreads();
        #pragma unroll
        for (int k = 0; k < BK; k++) {
            float a[8], bb[8];
            *(float4*)a       = *(float4*)&As[k][ty * 8];
            *(float4*)(a + 4) = *(float4*)&As[k][ty * 8 + 4];
            *(float4*)bb       = *(float4*)&Bs[k][tx * 8];
            *(float4*)(bb + 4) = *(float4*)&Bs[k][tx * 8 + 4];
            #pragma unroll
            for (int i = 0; i < 8; i++)
                #pragma unroll
                for (int j = 0; j < 8; j++) acc[i][j] = fmaf(a[i], bb[j], acc[i][j]);
        }
        __syncthreads();
    }
    #pragma unroll
    for (int i = 0; i < 8; i++) {
        int m = m0 + ty * 8 + i;
        float4 o0, o1;
        #pragma unroll
        for (int j = 0; j < 8; j++) {
            float vvv = acc[i][j];
            if (j < 4) ((float*)&o0)[j] = vvv; else ((float*)&o1)[j - 4] = vvv;
        }
        *(float4*)(Tb + (size_t)m * 1024 + n0 + tx * 8)     = o0;
        *(float4*)(Tb + (size_t)m * 1024 + n0 + tx * 8 + 4) = o1;
    }
}

/* ---------------- Sinkhorn ---------------- */
__global__ void zero_uv(float* u, float* v) {
    int i = blockIdx.x * blockDim.x + threadIdx.x;
    if (i < 4096) { u[i] = 0.f; v[i] = 0.f; }
}

__global__ __launch_bounds__(256) void u_update(const float* __restrict__ C,
                                                const float* __restrict__ v,
                                                float* __restrict__ u) {
    int b = blockIdx.y, i = blockIdx.x, t = threadIdx.x;
    const float4* C4 = (const float4*)(C + ((size_t)(b << 10) + i) * 1024);
    const float4* V4 = (const float4*)(v + (b << 10));
    float4 c = C4[t], vv = V4[t];
    float x0 = (vv.x - c.x) * INV_EPS;
    float x1 = (vv.y - c.y) * INV_EPS;
    float x2 = (vv.z - c.z) * INV_EPS;
    float x3 = (vv.w - c.w) * INV_EPS;
    float mx = fmaxf(fmaxf(x0, x1), fmaxf(x2, x3));
    __shared__ float redm[8], redq[8];
    mx = warpMax(mx);
    if ((t & 31) == 0) redm[t >> 5] = mx;
    __syncthreads();
    if (t < 32) {
        float z = (t < 8) ? redm[t] : -FLT_MAX;
        #pragma unroll
        for (int o = 4; o; o >>= 1) z = fmaxf(z, __shfl_xor_sync(0xffffffffu, z, o));
        if (t == 0) redm[0] = z;
    }
    __syncthreads();
    float bm = redm[0];
    float s = __expf(x0 - bm) + __expf(x1 - bm) + __expf(x2 - bm) + __expf(x3 - bm);
    s = warpSum(s);
    if ((t & 31) == 0) redq[t >> 5] = s;
    __syncthreads();
    if (t == 0) {
        float z = 0.f;
        #pragma unroll
        for (int q = 0; q < 8; q++) z += redq[q];
        u[(b << 10) + i] = EPS_S * (LOG_MU - (bm + __logf(z)));
    }
}

__global__ __launch_bounds__(256) void v_update(const float* __restrict__ C,
                                                const float* __restrict__ u,
                                                float* __restrict__ v) {
    int b = blockIdx.y;
    int tx = threadIdx.x, ty = threadIdx.y;
    int j = blockIdx.x * 32 + tx;
    const float* p = C + (size_t)b * 1048576 + j;
    const float* ub = u + (b << 10);
    float m0 = -FLT_MAX, s0 = 0.f, m1 = -FLT_MAX, s1 = 0.f;
    for (int i = ty; i < 1024; i += 16) {
        float xa = (ub[i] - p[(size_t)i << 10]) * INV_EPS;
        float xb = (ub[i + 8] - p[(size_t)(i + 8) << 10]) * INV_EPS;
        float n0 = fmaxf(m0, xa);
        s0 = s0 * __expf(m0 - n0) + __expf(xa - n0); m0 = n0;
        float n1 = fmaxf(m1, xb);
        s1 = s1 * __expf(m1 - n1) + __expf(xb - n1); m1 = n1;
    }
    float mm = fmaxf(m0, m1);
    float ss = s0 * __expf(m0 - mm) + s1 * __expf(m1 - mm);
    __shared__ float sm[8][32], sq[8][32];
    sm[ty][tx] = mm; sq[ty][tx] = ss;
    __syncthreads();
    if (ty == 0) {
        float M = mm, S = ss;
        #pragma unroll
        for (int q = 1; q < 8; q++) {
            float m2 = sm[q][tx], s2 = sq[q][tx];
            float nm = fmaxf(M, m2);
            S = S * __expf(M - nm) + s2 * __expf(m2 - nm);
            M = nm;
        }
        v[(b << 10) + j] = EPS_S * (LOG_MU - (M + __logf(S)));
    }
}

/* ---------------- per-(b,c) mean / 1/std of content ---------------- */
__global__ __launch_bounds__(128) void cmstd(const float* __restrict__ x,
                                             float* __restrict__ cm,
                                             float* __restrict__ rs) {
    int bc = blockIdx.x, t = threadIdx.x;
    const float* p = x + ((size_t)bc << 10);
    float s = 0.f, q = 0.f;
    #pragma unroll
    for (int l = 0; l < 8; l++) {
        float v = p[t + l * 128];
        s += v; q = fmaf(v, v, q);
    }
    s = warpSum(s); q = warpSum(q);
    __shared__ float rsm[4], rqm[4];
    if ((t & 31) == 0) { rsm[t >> 5] = s; rqm[t >> 5] = q; }
    __syncthreads();
    if (t == 0) {
        float S = rsm[0] + rsm[1] + rsm[2] + rsm[3];
        float Q = rqm[0] + rqm[1] + rqm[2] + rqm[3];
        float mean = S * (1.f / 1024.f);
        float var = Q * (1.f / 1024.f) - mean * mean;
        cm[bc] = mean;
        rs[bc] = rsqrtf(fmaxf(var, 0.f) + 1e-5f);
    }
}

/* ---------------- BatchNorm stats (train mode): scale/shift ---------------- */
__global__ __launch_bounds__(256) void bnstats(const float* __restrict__ x,
                                               const float* __restrict__ g,
                                               const float* __restrict__ be,
                                               int CO, float* __restrict__ scale,
                                               float* __restrict__ shift) {
    int c = blockIdx.x, t = threadIdx.x;
    float s = 0.f, q = 0.f;
    #pragma unroll
    for (int l = 0; l < 16; l++) {
        int idx = t + (l << 8);
        int bb = idx >> 10, p = idx & 1023;
        float v = x[((size_t)(bb * CO + c) << 10) + p];
        s += v; q = fmaf(v, v, q);
    }
    s = warpSum(s); q = warpSum(q);
    __shared__ float rsm[8], rqm[8];
    if ((t & 31) == 0) { rsm[t >> 5] = s; rqm[t >> 5] = q; }
    __syncthreads();
    if (t == 0) {
        float S = 0.f, Q = 0.f;
        #pragma unroll
        for (int w = 0; w < 8; w++) { S += rsm[w]; Q += rqm[w]; }
        float mean = S * (1.f / 4096.f);
        float var = Q * (1.f / 4096.f) - mean * mean;
        float sc = g[c] * rsqrtf(fmaxf(var, 0.f) + BN_EPS);
        scale[c] = sc;
        shift[c] = be[c] - mean * sc;
    }
}

/* ---------------- t = alpha * (content - cm) * rs + t ---------------- */
__global__ __launch_bounds__(256) void blend(float* __restrict__ t,
                                             const float* __restrict__ alpha,
                                             const float* __restrict__ content,
                                             const float* __restrict__ cm,
                                             const float* __restrict__ rs, int n4) {
    int i = blockIdx.x * 256 + threadIdx.x;
    if (i >= n4) return;
    int ch = i >> 8;
    float m = cm[ch], r = rs[ch];
    float4 a = ((const float4*)alpha)[i];
    float4 x = ((const float4*)content)[i];
    float4 tv = ((float4*)t)[i];
    tv.x = fmaf(a.x, (x.x - m) * r, tv.x);
    tv.y = fmaf(a.y, (x.y - m) * r, tv.y);
    tv.z = fmaf(a.z, (x.z - m) * r, tv.z);
    tv.w = fmaf(a.w, (x.w - m) * r, tv.w);
    ((float4*)t)[i] = tv;
}

/* ---------------- direct 3x3 conv, smem plane tiles (R1 layout + fixes) -----
   - 256 threads, SROWS=16 -> 2 row-tiles per image -> 2x blocks vs R1
   - weights stored s_w[ci][k][oc] -> LDS.128 broadcast loads
   - optional fused per-input-channel affine (BatchNorm apply)               */
template <int OCT, int SROWS, int NT, int CIT>
__global__ __launch_bounds__(NT) void conv3x3(
    const float* __restrict__ src0, const float* __restrict__ src1, int csplit,
    const float* __restrict__ sc, const float* __restrict__ sh,
    int CI, int CO, const float* __restrict__ W, const float* __restrict__ bias,
    float* __restrict__ out, int relu) {
    constexpr int NPIX = SROWS * 32;
    constexpr int PXT = NPIX / NT;
    __shared__ float s_in[CIT][SROWS + 2][34];
    __shared__ float s_w[CIT][9][OCT];
    int b = blockIdx.x, oc0 = blockIdx.y * OCT, r0 = blockIdx.z * SROWS;
    int tid = threadIdx.x;
    int rr[PXT], cc[PXT];
    #pragma unroll
    for (int p = 0; p < PXT; p++) {
        int px = tid + p * NT;
        rr[p] = px >> 5; cc[p] = px & 31;
    }
    float acc[OCT][PXT];
    #pragma unroll
    for (int o = 0; o < OCT; o++)
        #pragma unroll
        for (int p = 0; p < PXT; p++) acc[o][p] = 0.f;

    const int TOTIN = CIT * (SROWS + 2) * 34;
    const int TW = CIT * 9 * OCT;
    int use_aff = (sc != nullptr);

    #pragma unroll 1
    for (int ci0 = 0; ci0 < CI; ci0 += CIT) {
        #pragma unroll 1
        for (int idx = tid; idx < TOTIN; idx += NT) {
            int ci = idx / ((SROWS + 2) * 34);
            int rem = idx - ci * ((SROWS + 2) * 34);
            int r = rem / 34, c = rem - r * 34;
            int gy = r0 + r - 1, gx = c - 1;
            float v = 0.f;
            if ((unsigned)gy < 32u && (unsigned)gx < 32u) {
                int cig = ci0 + ci;
                const float* s = (cig < csplit)
                    ? (src0 + ((size_t)(b * csplit + cig) << 10))
                    : (src1 + ((size_t)(b * (CI - csplit) + (cig - csplit)) << 10));
                v = s[(gy << 5) + gx];
                if (use_aff) v = fmaf(v, sc[cig], sh[cig]);
            }
            (&s_in[0][0][0])[idx] = v;
        }
        #pragma unroll 1
        for (int idx = tid; idx < TW; idx += NT) {
            int ci = idx / (9 * OCT);
            int rem = idx - ci * (9 * OCT);
            int k = rem / OCT, oc = rem - k * OCT;
            float wv = 0.f;
            if (oc0 + oc < CO)
                wv = W[((size_t)(oc0 + oc) * CI + ci0 + ci) * 9 + k];
            (&s_w[0][0][0])[idx] = wv;
        }
        __syncthreads();
        #pragma unroll 1
        for (int ci = 0; ci < CIT; ci++) {
            #pragma unroll
            for (int ky = 0; ky < 3; ky++)
                #pragma unroll
                for (int kx = 0; kx < 3; kx++) {
                    float w[OCT];
                    #pragma unroll
                    for (int o4 = 0; o4 < OCT / 4; o4++)
                        *(float4*)&w[o4 * 4] = *(const float4*)&s_w[ci][ky * 3 + kx][o4 * 4];
                    #pragma unroll
                    for (int p = 0; p < PXT; p++) {
                        float v = s_in[ci][rr[p] + ky][cc[p] + kx];
                        #pragma unroll
                        for (int o = 0; o < OCT; o++)
                            acc[o][p] = fmaf(v, w[o], acc[o][p]);
                    }
                }
        }
        __syncthreads();
    }
    #pragma unroll
    for (int o = 0; o < OCT; o++) {
        if (oc0 + o >= CO) break;
        float bi = bias[oc0 + o];
        #pragma unroll
        for (int p = 0; p < PXT; p++) {
            float v = acc[o][p] + bi;
            if (relu) v = fmaxf(v, 0.f);
            out[((size_t)(b * CO + oc0 + o) << 10) + r0 * 32 + tid + p * NT] = v;
        }
    }
}

/* ---------------- host orchestration ---------------- */
extern "C" void kernel_launch(void* const* d_in, const int* in_sizes, int n_in,
                              void* d_out, int out_size) {
    const float* content = (const float*)d_in[0];
    const float* style   = (const float*)d_in[1];
    const float* w1 = (const float*)d_in[2];  const float* b1 = (const float*)d_in[3];
    const float* g1 = (const float*)d_in[4];  const float* be1 = (const float*)d_in[5];
    const float* w2 = (const float*)d_in[6];  const float* b2 = (const float*)d_in[7];
    const float* g2 = (const float*)d_in[8];  const float* be2 = (const float*)d_in[9];
    const float* w3 = (const float*)d_in[10]; const float* b3 = (const float*)d_in[11];
    const float* dw = (const float*)d_in[12]; const float* db = (const float*)d_in[13];
    float* out = (float*)d_out;
    (void)in_sizes; (void)n_in; (void)out_size;

    float *pC, *pu, *pv, *prnx, *prny, *pt, *pa1, *pa2, *palpha, *pcm, *prs, *pscale, *pshift;
    cudaGetSymbolAddress((void**)&pC, g_C);
    cudaGetSymbolAddress((void**)&pu, g_u);
    cudaGetSymbolAddress((void**)&pv, g_v);
    cudaGetSymbolAddress((void**)&prnx, g_rnx);
    cudaGetSymbolAddress((void**)&prny, g_rny);
    cudaGetSymbolAddress((void**)&pt, g_t);
    cudaGetSymbolAddress((void**)&pa1, g_a1);
    cudaGetSymbolAddress((void**)&pa2, g_a2);
    cudaGetSymbolAddress((void**)&palpha, g_alpha);
    cudaGetSymbolAddress((void**)&pcm, g_cm);
    cudaGetSymbolAddress((void**)&prs, g_rs);
    cudaGetSymbolAddress((void**)&pscale, g_scale);
    cudaGetSymbolAddress((void**)&pshift, g_shift);

    /* cosine-cost matrix */
    rownorm<<<dim3(4, 4), 256>>>(content, prnx);
    rownorm<<<dim3(4, 4), 256>>>(style, prny);
    gemm_tn_cost<<<dim3(8, 8, 4), 256>>>(content, style, prnx, prny, pC);

    /* Sinkhorn, 20 iterations */
    zero_uv<<<16, 256>>>(pu, pv);
    for (int it = 0; it < 20; it++) {
        u_update<<<dim3(1024, 4), 256>>>(pC, pv, pu);
        v_update<<<dim3(32, 4), dim3(32, 8)>>>(pC, pu, pv);
    }

    /* t = pi @ style_points, exp fused into B-tile load */
    gemm_nt_t<<<dim3(4, 8, 4), 256>>>(style, pC, pu, pv, pt);

    /* content per-channel mean/std */
    cmstd<<<2048, 128>>>(content, pcm, prs);

    /* alpha predictor (BN-apply fused into next conv's input load) */
    conv3x3<8, 16, 256, 8><<<dim3(4, 32, 2), 256>>>(pt, content, 512,
        nullptr, nullptr, 1024, 256, w1, b1, pa1, 1);
    bnstats<<<256, 256>>>(pa1, g1, be1, 256, pscale, pshift);
    conv3x3<8, 16, 256, 8><<<dim3(4, 32, 2), 256>>>(pa1, pa1, 256,
        pscale, pshift, 256, 256, w2, b2, pa2, 1);
    bnstats<<<256, 256>>>(pa2, g2, be2, 256, pscale, pshift);
    conv3x3<8, 16, 256, 8><<<dim3(4, 64, 2), 256>>>(pa2, pa2, 256,
        pscale, pshift, 256, 512, w3, b3, palpha, 0);

    /* t = alpha * c_normed + t, then decoder conv -> out */
    blend<<<2048, 256>>>(pt, palpha, content, pcm, prs, 4 * 512 * 256);
    conv3x3<4, 4, 128, 8><<<dim3(4, 1, 8), 128>>>(pt, pt, 512,
        nullptr, nullptr, 512, 3, dw, db, out, 0);
}